// round 15
// baseline (speedup 1.0000x reference)
#include <cuda_runtime.h>

// ---------------------------------------------------------------------------
// DctLayer FINAL — converged. Identical source measured 6x:
// app 78.2-79.8 us (mean ~78.8, sigma ~0.6), ncu 73.1-75.2 us,
// DRAM 74.6-76.7% (spread == documented run-to-run LTS/DRAM variation).
//
// Algorithm: per 8x8 block,
//   out0 = L*B*L^T, out1 = L*B - out0, out2 = H*B*L^T, out3 = H*B - out2,
// with L = rank-4 DCT low-pass projector, H = I - L. Corner masks are
// separable and the DCT orthonormal, so forward-DCT/mask/inverse-DCT
// collapses to 3 tiny constant matmuls + subtractions per block.
//
// Pure HBM-streaming problem: 100.7 MB read + 402.7 MB written (minimal);
// ~6.8 TB/s effective = practical DRAM ceiling for a 4:1 write:read mix.
// Probed and rejected: occupancy up (R7 neutral), store regrouping (R8 -2%),
// persistent CTAs (R9 -13%), write-back stores (R12 neutral), v8 256-bit
// accesses (paper-rejected: doubles live state -> known-slower 2-CTA regime).
//
// Layout: 2 threads per 8x8 block; even lane owns cols 0-3, odd lane owns
// cols 4-7 with REVERSED slot convention (slot j = col 7-j) ->
//   - every LDG/STG.128 is 512B-contiguous per warp (4 L1 wavefronts)
//   - vertical stage shuffle-free in butterfly (s,d) space (32 live floats;
//     row-pairs materialized/stored/freed -> 80 regs, 3 CTAs/SM)
//   - horizontal butterfly is one shfl_xor(,1); the parity sign on d cancels
//     against needing e+o (even) / e-o (odd): one uniform formula.
//
// L*a = butterfly + two 4x4 matvecs with compile-time constants:
//   E[i][x] = 0.125 + 0.25*g[i]*g[x],          g  = [c2, c6, -c6, -c2]
//   O[i][x] = 0.25*(h1[i]h1[x] + h3[i]h3[x]),  h1 = [c1,c3,c5,c7], h3 = [c3,-c7,-c1,-c5]
// (cm = cos(m*pi/16)); rel_err 7.6e-7 vs reference.
// ---------------------------------------------------------------------------

#define E00 0.33838834764831845f
#define E01 0.21338834764831843f
#define E02 0.03661165235168157f
#define E03 (-0.08838834764831845f)
#define E11 0.16161165235168156f
#define E12 0.08838834764831844f
#define E13 0.03661165235168157f
#define E22 0.16161165235168156f
#define E23 0.21338834764831843f
#define E33 0.33838834764831845f

#define O00 0.41332037060954707f
#define O01 0.16332037060954707f
#define O02 (-0.06764951251827464f)
#define O03 (-0.06764951251827464f)
#define O11 0.18235048748172537f
#define O12 0.16332037060954707f
#define O13 0.06764951251827464f
#define O22 0.31764951251827466f
#define O23 0.16332037060954707f
#define O33 0.08667962939045293f

__device__ constexpr float Ec[4][4] = {
    { E00, E01, E02, E03 },
    { E01, E11, E12, E13 },
    { E02, E12, E22, E23 },
    { E03, E13, E23, E33 } };
__device__ constexpr float Oc[4][4] = {
    { O00, O01, O02, O03 },
    { O01, O11, O12, O13 },
    { O02, O12, O22, O23 },
    { O03, O13, O23, O33 } };

// Horizontal half-row mix: lane-pair exchange is the butterfly partner in
// both parities; the parity sign on d cancels against e +/- o.
__device__ __forceinline__ void hmix4(float m0, float m1, float m2, float m3,
                                      float& t0, float& t1, float& t2, float& t3) {
    float r0 = __shfl_xor_sync(0xffffffffu, m0, 1);
    float r1 = __shfl_xor_sync(0xffffffffu, m1, 1);
    float r2 = __shfl_xor_sync(0xffffffffu, m2, 1);
    float r3 = __shfl_xor_sync(0xffffffffu, m3, 1);

    float s0 = m0 + r0, s1 = m1 + r1, s2 = m2 + r2, s3 = m3 + r3;
    float d0 = m0 - r0, d1 = m1 - r1, d2 = m2 - r2, d3 = m3 - r3;

    t0 = E00*s0 + E01*s1 + E02*s2 + E03*s3 + O00*d0 + O01*d1 + O02*d2 + O03*d3;
    t1 = E01*s0 + E11*s1 + E12*s2 + E13*s3 + O01*d0 + O11*d1 + O12*d2 + O13*d3;
    t2 = E02*s0 + E12*s1 + E22*s2 + E23*s3 + O02*d0 + O12*d1 + O22*d2 + O23*d3;
    t3 = E03*s0 + E13*s1 + E23*s2 + E33*s3 + O03*d0 + O13*d1 + O23*d2 + O33*d3;
}

__device__ __forceinline__ float4 marsh(int half, float a0, float a1, float a2, float a3) {
    return half ? make_float4(a3, a2, a1, a0) : make_float4(a0, a1, a2, a3);
}

// Fold a (row, 7-row) float4 pair into butterfly space (odd-lane slot reversal).
__device__ __forceinline__ void fold(float4 qt, float4 qb, int half,
                                     float s[4], float d[4]) {
    float at0 = half ? qt.w : qt.x, at1 = half ? qt.z : qt.y;
    float at2 = half ? qt.y : qt.z, at3 = half ? qt.x : qt.w;
    float ab0 = half ? qb.w : qb.x, ab1 = half ? qb.z : qb.y;
    float ab2 = half ? qb.y : qb.z, ab3 = half ? qb.x : qb.w;
    s[0] = at0 + ab0;  d[0] = at0 - ab0;
    s[1] = at1 + ab1;  d[1] = at1 - ab1;
    s[2] = at2 + ab2;  d[2] = at2 - ab2;
    s[3] = at3 + ab3;  d[3] = at3 - ab3;
}

// Vertical row-pair (rows RR and 7-RR) from s/d space.
template <int RR>
__device__ __forceinline__ void vpair(const float s[4][4], const float d[4][4],
                                      float loT[4], float loB[4],
                                      float hiT[4], float hiB[4]) {
#pragma unroll
    for (int c = 0; c < 4; ++c) {
        float e = Ec[RR][0]*s[0][c] + Ec[RR][1]*s[1][c]
                + Ec[RR][2]*s[2][c] + Ec[RR][3]*s[3][c];
        float o = Oc[RR][0]*d[0][c] + Oc[RR][1]*d[1][c]
                + Oc[RR][2]*d[2][c] + Oc[RR][3]*d[3][c];
        loT[c] = e + o;
        loB[c] = e - o;
        hiT[c] = 0.5f*s[RR][c] + 0.5f*d[RR][c] - loT[c];
        hiB[c] = 0.5f*s[RR][c] - 0.5f*d[RR][c] - loB[c];
    }
}

// 2 threads per 8x8 block. 393216 blocks -> 786432 threads -> 3072 CTAs.
__global__ void __launch_bounds__(256, 3)
dct_corner_kernel(const float* __restrict__ x, float* __restrict__ out)
{
    int t    = blockIdx.x * 256 + threadIdx.x;
    int half = t & 1;                 // 0: cols 0-3, 1: cols 4-7 (reversed slots)
    int p    = t >> 1;                // block index
    int bx   = p & 63;
    int by   = (p >> 6) & 63;
    int ch   = p >> 12;

    const float* src = x + ((size_t)ch << 18) + (size_t)(by << 3) * 512
                         + (bx << 3) + (half << 2);

    // Front-issue all 8 row loads (MLP 8); fold each (r, 7-r) pair as it lands.
    float4 q0 = __ldcs((const float4*)(src));
    float4 q7 = __ldcs((const float4*)(src + 7 * 512));
    float4 q1 = __ldcs((const float4*)(src + 1 * 512));
    float4 q6 = __ldcs((const float4*)(src + 6 * 512));
    float4 q2 = __ldcs((const float4*)(src + 2 * 512));
    float4 q5 = __ldcs((const float4*)(src + 5 * 512));
    float4 q3 = __ldcs((const float4*)(src + 3 * 512));
    float4 q4 = __ldcs((const float4*)(src + 4 * 512));

    float s[4][4], d[4][4];
    fold(q0, q7, half, s[0], d[0]);
    fold(q1, q6, half, s[1], d[1]);
    fold(q2, q5, half, s[2], d[2]);
    fold(q3, q4, half, s[3], d[3]);

    const size_t PL = (size_t)96 * 512 * 512;
    float* pO = out + ((size_t)ch << 18) + (size_t)(by << 3) * 512
                    + (bx << 3) + (half << 2);

#define DO_PAIR(RR)                                                            \
    {                                                                          \
        float loT[4], loB[4], hiT[4], hiB[4];                                  \
        vpair<RR>(s, d, loT, loB, hiT, hiB);                                   \
        float* pT = pO + (size_t)(RR) * 512;                                   \
        float* pB = pO + (size_t)(7 - (RR)) * 512;                             \
        float t0, t1, t2, t3;                                                  \
        hmix4(loT[0], loT[1], loT[2], loT[3], t0, t1, t2, t3);                 \
        __stcs((float4*)(pT),      marsh(half, t0, t1, t2, t3));               \
        __stcs((float4*)(pT + PL), marsh(half, loT[0]-t0, loT[1]-t1,           \
                                               loT[2]-t2, loT[3]-t3));         \
        hmix4(hiT[0], hiT[1], hiT[2], hiT[3], t0, t1, t2, t3);                 \
        __stcs((float4*)(pT + 2*PL), marsh(half, t0, t1, t2, t3));             \
        __stcs((float4*)(pT + 3*PL), marsh(half, hiT[0]-t0, hiT[1]-t1,         \
                                                 hiT[2]-t2, hiT[3]-t3));       \
        hmix4(loB[0], loB[1], loB[2], loB[3], t0, t1, t2, t3);                 \
        __stcs((float4*)(pB),      marsh(half, t0, t1, t2, t3));               \
        __stcs((float4*)(pB + PL), marsh(half, loB[0]-t0, loB[1]-t1,           \
                                               loB[2]-t2, loB[3]-t3));         \
        hmix4(hiB[0], hiB[1], hiB[2], hiB[3], t0, t1, t2, t3);                 \
        __stcs((float4*)(pB + 2*PL), marsh(half, t0, t1, t2, t3));             \
        __stcs((float4*)(pB + 3*PL), marsh(half, hiB[0]-t0, hiB[1]-t1,         \
                                                 hiB[2]-t2, hiB[3]-t3));       \
    }

    DO_PAIR(0)
    DO_PAIR(1)
    DO_PAIR(2)
    DO_PAIR(3)
#undef DO_PAIR
}

extern "C" void kernel_launch(void* const* d_in, const int* in_sizes, int n_in,
                              void* d_out, int out_size) {
    const float* x = (const float*)d_in[0];
    float* out     = (float*)d_out;

    // 2 threads per 8x8 block
    int total_threads = (in_sizes[0] / 64) * 2;     // 786432
    int grid = total_threads / 256;                 // 3072
    dct_corner_kernel<<<grid, 256>>>(x, out);
}

// round 16
// speedup vs baseline: 1.0189x; 1.0189x over previous
#include <cuda_runtime.h>

// ---------------------------------------------------------------------------
// DctLayer: per 8x8 block,
//   out0 = L*B*L^T, out1 = L*B - out0, out2 = H*B*L^T, out3 = H*B - out2,
// with L = rank-4 DCT low-pass projector, H = I - L. Corner masks separable,
// DCT orthonormal -> forward-DCT/mask/inverse-DCT collapses to 3 tiny
// constant matmuls + subtractions per block. Pure HBM streaming (~503 MB
// minimal; ~6.8 TB/s effective = practical DRAM ceiling for 4:1 write:read).
//
// R16 probe (last untouched knob): CTA size 256 -> 128 threads,
// __launch_bounds__(128, 6). Warps/SM (24), regs (80), and the per-warp
// memory pattern are IDENTICAL (all communication is intra-warp shfl_xor(,1);
// all LDG/STG.128 512B-contiguous per warp). Only the scheduling quantum
// changes: 6144 CTAs -> finer CLC distribution, more de-correlated
// load/store phases per SM, smaller tail imbalance.
//
// Layout: 2 threads per 8x8 block; even lane cols 0-3, odd lane cols 4-7
// slot-reversed (slot j = col 7-j); vertical stage shuffle-free in butterfly
// (s,d) space; horizontal butterfly one shfl_xor(,1) with parity sign
// cancelling against e +/- o. rel_err 7.6e-7 vs reference.
// ---------------------------------------------------------------------------

#define E00 0.33838834764831845f
#define E01 0.21338834764831843f
#define E02 0.03661165235168157f
#define E03 (-0.08838834764831845f)
#define E11 0.16161165235168156f
#define E12 0.08838834764831844f
#define E13 0.03661165235168157f
#define E22 0.16161165235168156f
#define E23 0.21338834764831843f
#define E33 0.33838834764831845f

#define O00 0.41332037060954707f
#define O01 0.16332037060954707f
#define O02 (-0.06764951251827464f)
#define O03 (-0.06764951251827464f)
#define O11 0.18235048748172537f
#define O12 0.16332037060954707f
#define O13 0.06764951251827464f
#define O22 0.31764951251827466f
#define O23 0.16332037060954707f
#define O33 0.08667962939045293f

__device__ constexpr float Ec[4][4] = {
    { E00, E01, E02, E03 },
    { E01, E11, E12, E13 },
    { E02, E12, E22, E23 },
    { E03, E13, E23, E33 } };
__device__ constexpr float Oc[4][4] = {
    { O00, O01, O02, O03 },
    { O01, O11, O12, O13 },
    { O02, O12, O22, O23 },
    { O03, O13, O23, O33 } };

// Horizontal half-row mix: lane-pair exchange is the butterfly partner in
// both parities; the parity sign on d cancels against e +/- o.
__device__ __forceinline__ void hmix4(float m0, float m1, float m2, float m3,
                                      float& t0, float& t1, float& t2, float& t3) {
    float r0 = __shfl_xor_sync(0xffffffffu, m0, 1);
    float r1 = __shfl_xor_sync(0xffffffffu, m1, 1);
    float r2 = __shfl_xor_sync(0xffffffffu, m2, 1);
    float r3 = __shfl_xor_sync(0xffffffffu, m3, 1);

    float s0 = m0 + r0, s1 = m1 + r1, s2 = m2 + r2, s3 = m3 + r3;
    float d0 = m0 - r0, d1 = m1 - r1, d2 = m2 - r2, d3 = m3 - r3;

    t0 = E00*s0 + E01*s1 + E02*s2 + E03*s3 + O00*d0 + O01*d1 + O02*d2 + O03*d3;
    t1 = E01*s0 + E11*s1 + E12*s2 + E13*s3 + O01*d0 + O11*d1 + O12*d2 + O13*d3;
    t2 = E02*s0 + E12*s1 + E22*s2 + E23*s3 + O02*d0 + O12*d1 + O22*d2 + O23*d3;
    t3 = E03*s0 + E13*s1 + E23*s2 + E33*s3 + O03*d0 + O13*d1 + O23*d2 + O33*d3;
}

__device__ __forceinline__ float4 marsh(int half, float a0, float a1, float a2, float a3) {
    return half ? make_float4(a3, a2, a1, a0) : make_float4(a0, a1, a2, a3);
}

// Fold a (row, 7-row) float4 pair into butterfly space (odd-lane slot reversal).
__device__ __forceinline__ void fold(float4 qt, float4 qb, int half,
                                     float s[4], float d[4]) {
    float at0 = half ? qt.w : qt.x, at1 = half ? qt.z : qt.y;
    float at2 = half ? qt.y : qt.z, at3 = half ? qt.x : qt.w;
    float ab0 = half ? qb.w : qb.x, ab1 = half ? qb.z : qb.y;
    float ab2 = half ? qb.y : qb.z, ab3 = half ? qb.x : qb.w;
    s[0] = at0 + ab0;  d[0] = at0 - ab0;
    s[1] = at1 + ab1;  d[1] = at1 - ab1;
    s[2] = at2 + ab2;  d[2] = at2 - ab2;
    s[3] = at3 + ab3;  d[3] = at3 - ab3;
}

// Vertical row-pair (rows RR and 7-RR) from s/d space.
template <int RR>
__device__ __forceinline__ void vpair(const float s[4][4], const float d[4][4],
                                      float loT[4], float loB[4],
                                      float hiT[4], float hiB[4]) {
#pragma unroll
    for (int c = 0; c < 4; ++c) {
        float e = Ec[RR][0]*s[0][c] + Ec[RR][1]*s[1][c]
                + Ec[RR][2]*s[2][c] + Ec[RR][3]*s[3][c];
        float o = Oc[RR][0]*d[0][c] + Oc[RR][1]*d[1][c]
                + Oc[RR][2]*d[2][c] + Oc[RR][3]*d[3][c];
        loT[c] = e + o;
        loB[c] = e - o;
        hiT[c] = 0.5f*s[RR][c] + 0.5f*d[RR][c] - loT[c];
        hiB[c] = 0.5f*s[RR][c] - 0.5f*d[RR][c] - loB[c];
    }
}

// 2 threads per 8x8 block. 786432 threads -> 6144 CTAs of 128.
__global__ void __launch_bounds__(128, 6)
dct_corner_kernel(const float* __restrict__ x, float* __restrict__ out)
{
    int t    = blockIdx.x * 128 + threadIdx.x;
    int half = t & 1;                 // 0: cols 0-3, 1: cols 4-7 (reversed slots)
    int p    = t >> 1;                // block index
    int bx   = p & 63;
    int by   = (p >> 6) & 63;
    int ch   = p >> 12;

    const float* src = x + ((size_t)ch << 18) + (size_t)(by << 3) * 512
                         + (bx << 3) + (half << 2);

    // Front-issue all 8 row loads (MLP 8); fold each (r, 7-r) pair as it lands.
    float4 q0 = __ldcs((const float4*)(src));
    float4 q7 = __ldcs((const float4*)(src + 7 * 512));
    float4 q1 = __ldcs((const float4*)(src + 1 * 512));
    float4 q6 = __ldcs((const float4*)(src + 6 * 512));
    float4 q2 = __ldcs((const float4*)(src + 2 * 512));
    float4 q5 = __ldcs((const float4*)(src + 5 * 512));
    float4 q3 = __ldcs((const float4*)(src + 3 * 512));
    float4 q4 = __ldcs((const float4*)(src + 4 * 512));

    float s[4][4], d[4][4];
    fold(q0, q7, half, s[0], d[0]);
    fold(q1, q6, half, s[1], d[1]);
    fold(q2, q5, half, s[2], d[2]);
    fold(q3, q4, half, s[3], d[3]);

    const size_t PL = (size_t)96 * 512 * 512;
    float* pO = out + ((size_t)ch << 18) + (size_t)(by << 3) * 512
                    + (bx << 3) + (half << 2);

#define DO_PAIR(RR)                                                            \
    {                                                                          \
        float loT[4], loB[4], hiT[4], hiB[4];                                  \
        vpair<RR>(s, d, loT, loB, hiT, hiB);                                   \
        float* pT = pO + (size_t)(RR) * 512;                                   \
        float* pB = pO + (size_t)(7 - (RR)) * 512;                             \
        float t0, t1, t2, t3;                                                  \
        hmix4(loT[0], loT[1], loT[2], loT[3], t0, t1, t2, t3);                 \
        __stcs((float4*)(pT),      marsh(half, t0, t1, t2, t3));               \
        __stcs((float4*)(pT + PL), marsh(half, loT[0]-t0, loT[1]-t1,           \
                                               loT[2]-t2, loT[3]-t3));         \
        hmix4(hiT[0], hiT[1], hiT[2], hiT[3], t0, t1, t2, t3);                 \
        __stcs((float4*)(pT + 2*PL), marsh(half, t0, t1, t2, t3));             \
        __stcs((float4*)(pT + 3*PL), marsh(half, hiT[0]-t0, hiT[1]-t1,         \
                                                 hiT[2]-t2, hiT[3]-t3));       \
        hmix4(loB[0], loB[1], loB[2], loB[3], t0, t1, t2, t3);                 \
        __stcs((float4*)(pB),      marsh(half, t0, t1, t2, t3));               \
        __stcs((float4*)(pB + PL), marsh(half, loB[0]-t0, loB[1]-t1,           \
                                               loB[2]-t2, loB[3]-t3));         \
        hmix4(hiB[0], hiB[1], hiB[2], hiB[3], t0, t1, t2, t3);                 \
        __stcs((float4*)(pB + 2*PL), marsh(half, t0, t1, t2, t3));             \
        __stcs((float4*)(pB + 3*PL), marsh(half, hiB[0]-t0, hiB[1]-t1,         \
                                                 hiB[2]-t2, hiB[3]-t3));       \
    }

    DO_PAIR(0)
    DO_PAIR(1)
    DO_PAIR(2)
    DO_PAIR(3)
#undef DO_PAIR
}

extern "C" void kernel_launch(void* const* d_in, const int* in_sizes, int n_in,
                              void* d_out, int out_size) {
    const float* x = (const float*)d_in[0];
    float* out     = (float*)d_out;

    // 2 threads per 8x8 block, 128-thread CTAs
    int total_threads = (in_sizes[0] / 64) * 2;     // 786432
    int grid = total_threads / 128;                 // 6144
    dct_corner_kernel<<<grid, 128>>>(x, out);
}

// round 17
// speedup vs baseline: 1.0193x; 1.0004x over previous
#include <cuda_runtime.h>

// ---------------------------------------------------------------------------
// DctLayer: per 8x8 block,
//   out0 = L*B*L^T, out1 = L*B - out0, out2 = H*B*L^T, out3 = H*B - out2,
// with L = rank-4 DCT low-pass projector, H = I - L. Corner masks separable,
// DCT orthonormal -> forward-DCT/mask/inverse-DCT collapses to 3 tiny
// constant matmuls + subtractions per block. Pure HBM streaming (~503 MB
// minimal; ~6.8 TB/s effective = practical DRAM ceiling for 4:1 write:read).
//
// R17: CTA-granularity sweep, step 3. 256 -> 128 threads gained ~1 us
// (77.9 vs 78.2-79.8 distribution) via finer CLC quanta / de-correlated
// load-store phases per SM. This round: 64-thread CTAs,
// __launch_bounds__(64, 12), 12288 CTAs. Warps/SM (24), regs (80), and the
// per-warp memory pattern are IDENTICAL (all communication is intra-warp
// shfl_xor(,1); all LDG/STG.128 512B-contiguous per warp).
//
// Layout: 2 threads per 8x8 block; even lane cols 0-3, odd lane cols 4-7
// slot-reversed (slot j = col 7-j); vertical stage shuffle-free in butterfly
// (s,d) space; horizontal butterfly one shfl_xor(,1) with parity sign
// cancelling against e +/- o. rel_err 7.6e-7 vs reference.
// ---------------------------------------------------------------------------

#define E00 0.33838834764831845f
#define E01 0.21338834764831843f
#define E02 0.03661165235168157f
#define E03 (-0.08838834764831845f)
#define E11 0.16161165235168156f
#define E12 0.08838834764831844f
#define E13 0.03661165235168157f
#define E22 0.16161165235168156f
#define E23 0.21338834764831843f
#define E33 0.33838834764831845f

#define O00 0.41332037060954707f
#define O01 0.16332037060954707f
#define O02 (-0.06764951251827464f)
#define O03 (-0.06764951251827464f)
#define O11 0.18235048748172537f
#define O12 0.16332037060954707f
#define O13 0.06764951251827464f
#define O22 0.31764951251827466f
#define O23 0.16332037060954707f
#define O33 0.08667962939045293f

__device__ constexpr float Ec[4][4] = {
    { E00, E01, E02, E03 },
    { E01, E11, E12, E13 },
    { E02, E12, E22, E23 },
    { E03, E13, E23, E33 } };
__device__ constexpr float Oc[4][4] = {
    { O00, O01, O02, O03 },
    { O01, O11, O12, O13 },
    { O02, O12, O22, O23 },
    { O03, O13, O23, O33 } };

// Horizontal half-row mix: lane-pair exchange is the butterfly partner in
// both parities; the parity sign on d cancels against e +/- o.
__device__ __forceinline__ void hmix4(float m0, float m1, float m2, float m3,
                                      float& t0, float& t1, float& t2, float& t3) {
    float r0 = __shfl_xor_sync(0xffffffffu, m0, 1);
    float r1 = __shfl_xor_sync(0xffffffffu, m1, 1);
    float r2 = __shfl_xor_sync(0xffffffffu, m2, 1);
    float r3 = __shfl_xor_sync(0xffffffffu, m3, 1);

    float s0 = m0 + r0, s1 = m1 + r1, s2 = m2 + r2, s3 = m3 + r3;
    float d0 = m0 - r0, d1 = m1 - r1, d2 = m2 - r2, d3 = m3 - r3;

    t0 = E00*s0 + E01*s1 + E02*s2 + E03*s3 + O00*d0 + O01*d1 + O02*d2 + O03*d3;
    t1 = E01*s0 + E11*s1 + E12*s2 + E13*s3 + O01*d0 + O11*d1 + O12*d2 + O13*d3;
    t2 = E02*s0 + E12*s1 + E22*s2 + E23*s3 + O02*d0 + O12*d1 + O22*d2 + O23*d3;
    t3 = E03*s0 + E13*s1 + E23*s2 + E33*s3 + O03*d0 + O13*d1 + O23*d2 + O33*d3;
}

__device__ __forceinline__ float4 marsh(int half, float a0, float a1, float a2, float a3) {
    return half ? make_float4(a3, a2, a1, a0) : make_float4(a0, a1, a2, a3);
}

// Fold a (row, 7-row) float4 pair into butterfly space (odd-lane slot reversal).
__device__ __forceinline__ void fold(float4 qt, float4 qb, int half,
                                     float s[4], float d[4]) {
    float at0 = half ? qt.w : qt.x, at1 = half ? qt.z : qt.y;
    float at2 = half ? qt.y : qt.z, at3 = half ? qt.x : qt.w;
    float ab0 = half ? qb.w : qb.x, ab1 = half ? qb.z : qb.y;
    float ab2 = half ? qb.y : qb.z, ab3 = half ? qb.x : qb.w;
    s[0] = at0 + ab0;  d[0] = at0 - ab0;
    s[1] = at1 + ab1;  d[1] = at1 - ab1;
    s[2] = at2 + ab2;  d[2] = at2 - ab2;
    s[3] = at3 + ab3;  d[3] = at3 - ab3;
}

// Vertical row-pair (rows RR and 7-RR) from s/d space.
template <int RR>
__device__ __forceinline__ void vpair(const float s[4][4], const float d[4][4],
                                      float loT[4], float loB[4],
                                      float hiT[4], float hiB[4]) {
#pragma unroll
    for (int c = 0; c < 4; ++c) {
        float e = Ec[RR][0]*s[0][c] + Ec[RR][1]*s[1][c]
                + Ec[RR][2]*s[2][c] + Ec[RR][3]*s[3][c];
        float o = Oc[RR][0]*d[0][c] + Oc[RR][1]*d[1][c]
                + Oc[RR][2]*d[2][c] + Oc[RR][3]*d[3][c];
        loT[c] = e + o;
        loB[c] = e - o;
        hiT[c] = 0.5f*s[RR][c] + 0.5f*d[RR][c] - loT[c];
        hiB[c] = 0.5f*s[RR][c] - 0.5f*d[RR][c] - loB[c];
    }
}

// 2 threads per 8x8 block. 786432 threads -> 12288 CTAs of 64.
__global__ void __launch_bounds__(64, 12)
dct_corner_kernel(const float* __restrict__ x, float* __restrict__ out)
{
    int t    = blockIdx.x * 64 + threadIdx.x;
    int half = t & 1;                 // 0: cols 0-3, 1: cols 4-7 (reversed slots)
    int p    = t >> 1;                // block index
    int bx   = p & 63;
    int by   = (p >> 6) & 63;
    int ch   = p >> 12;

    const float* src = x + ((size_t)ch << 18) + (size_t)(by << 3) * 512
                         + (bx << 3) + (half << 2);

    // Front-issue all 8 row loads (MLP 8); fold each (r, 7-r) pair as it lands.
    float4 q0 = __ldcs((const float4*)(src));
    float4 q7 = __ldcs((const float4*)(src + 7 * 512));
    float4 q1 = __ldcs((const float4*)(src + 1 * 512));
    float4 q6 = __ldcs((const float4*)(src + 6 * 512));
    float4 q2 = __ldcs((const float4*)(src + 2 * 512));
    float4 q5 = __ldcs((const float4*)(src + 5 * 512));
    float4 q3 = __ldcs((const float4*)(src + 3 * 512));
    float4 q4 = __ldcs((const float4*)(src + 4 * 512));

    float s[4][4], d[4][4];
    fold(q0, q7, half, s[0], d[0]);
    fold(q1, q6, half, s[1], d[1]);
    fold(q2, q5, half, s[2], d[2]);
    fold(q3, q4, half, s[3], d[3]);

    const size_t PL = (size_t)96 * 512 * 512;
    float* pO = out + ((size_t)ch << 18) + (size_t)(by << 3) * 512
                    + (bx << 3) + (half << 2);

#define DO_PAIR(RR)                                                            \
    {                                                                          \
        float loT[4], loB[4], hiT[4], hiB[4];                                  \
        vpair<RR>(s, d, loT, loB, hiT, hiB);                                   \
        float* pT = pO + (size_t)(RR) * 512;                                   \
        float* pB = pO + (size_t)(7 - (RR)) * 512;                             \
        float t0, t1, t2, t3;                                                  \
        hmix4(loT[0], loT[1], loT[2], loT[3], t0, t1, t2, t3);                 \
        __stcs((float4*)(pT),      marsh(half, t0, t1, t2, t3));               \
        __stcs((float4*)(pT + PL), marsh(half, loT[0]-t0, loT[1]-t1,           \
                                               loT[2]-t2, loT[3]-t3));         \
        hmix4(hiT[0], hiT[1], hiT[2], hiT[3], t0, t1, t2, t3);                 \
        __stcs((float4*)(pT + 2*PL), marsh(half, t0, t1, t2, t3));             \
        __stcs((float4*)(pT + 3*PL), marsh(half, hiT[0]-t0, hiT[1]-t1,         \
                                                 hiT[2]-t2, hiT[3]-t3));       \
        hmix4(loB[0], loB[1], loB[2], loB[3], t0, t1, t2, t3);                 \
        __stcs((float4*)(pB),      marsh(half, t0, t1, t2, t3));               \
        __stcs((float4*)(pB + PL), marsh(half, loB[0]-t0, loB[1]-t1,           \
                                               loB[2]-t2, loB[3]-t3));         \
        hmix4(hiB[0], hiB[1], hiB[2], hiB[3], t0, t1, t2, t3);                 \
        __stcs((float4*)(pB + 2*PL), marsh(half, t0, t1, t2, t3));             \
        __stcs((float4*)(pB + 3*PL), marsh(half, hiB[0]-t0, hiB[1]-t1,         \
                                                 hiB[2]-t2, hiB[3]-t3));       \
    }

    DO_PAIR(0)
    DO_PAIR(1)
    DO_PAIR(2)
    DO_PAIR(3)
#undef DO_PAIR
}

extern "C" void kernel_launch(void* const* d_in, const int* in_sizes, int n_in,
                              void* d_out, int out_size) {
    const float* x = (const float*)d_in[0];
    float* out     = (float*)d_out;

    // 2 threads per 8x8 block, 64-thread CTAs
    int total_threads = (in_sizes[0] / 64) * 2;     // 786432
    int grid = total_threads / 64;                  // 12288
    dct_corner_kernel<<<grid, 64>>>(x, out);
}